// round 14
// baseline (speedup 1.0000x reference)
#include <cuda_runtime.h>
#include <cstdint>

#define NN 16384
#define DD 8
#define SS 8192
#define TI 64          // unique i-rows per tile (64-aligned padding)
#define TJ 256         // raw j-cols per tile (= blockDim.x)
#define NTJ (NN / TJ)  // 64 j-tiles (all raw columns)

// -------- scratch (no allocations; zero-init at load; self-restoring) --------
__device__ int    g_hist[NN];        // re-zeroed by k_emit each run
__device__ int    g_bsum[128];       // overwritten by k_scan1 each run
__device__ int    g_ucols[SS];       // sorted unique sample values (i-padded)
__device__ float  g_cntf[SS];        // unique multiplicities (0 for padding)
__device__ float  g_cntraw[NN];      // per-RAW-column multiplicity (0 default;
                                     //   unique entries rewritten identically each run)
__device__ float  g_z[SS * DD];      // gathered z (unique, sorted)
__device__ float  g_sq[SS];          // |z|^2 (unique, sorted)
__device__ int    g_meta[4];         // U, n_ti, -, -
__device__ double g_acc;             // reset by k_final each run

// -------- packed f32x2 helpers --------
__device__ __forceinline__ unsigned long long pk2(float lo, float hi) {
    unsigned long long r;
    asm("mov.b64 %0, {%1, %2};" : "=l"(r) : "f"(lo), "f"(hi));
    return r;
}
__device__ __forceinline__ void upk2(unsigned long long v, float& lo, float& hi) {
    asm("mov.b64 {%0, %1}, %2;" : "=f"(lo), "=f"(hi) : "l"(v));
}
__device__ __forceinline__ unsigned long long fma2(unsigned long long a,
                                                   unsigned long long b,
                                                   unsigned long long c) {
    unsigned long long d;
    asm("fma.rn.f32x2 %0, %1, %2, %3;" : "=l"(d) : "l"(a), "l"(b), "l"(c));
    return d;
}
__device__ __forceinline__ unsigned long long add2(unsigned long long a,
                                                   unsigned long long b) {
    unsigned long long d;
    asm("add.rn.f32x2 %0, %1, %2;" : "=l"(d) : "l"(a), "l"(b));
    return d;
}
__device__ __forceinline__ float fsqrt_ap(float x) {
    float r; asm("sqrt.approx.f32 %0, %1;" : "=f"(r) : "f"(x)); return r;
}
__device__ __forceinline__ float frcp_ap(float x) {
    float r; asm("rcp.approx.f32 %0, %1;" : "=f"(r) : "f"(x)); return r;
}

// -------- 1) histogram + per-sample diagonal correction --------
__global__ void __launch_bounds__(256) k_hist(const int* __restrict__ idx,
                                              const float* __restrict__ rel) {
    __shared__ double dred[8];
    int t = blockIdx.x * blockDim.x + threadIdx.x;
    int v = idx[t];
    atomicAdd(&g_hist[v], 1);
    float r = __ldg(rel + (size_t)v * NN + v);
    double dsum = (double)r * (double)r / 5.0 - (double)r;
#pragma unroll
    for (int o = 16; o > 0; o >>= 1)
        dsum += __shfl_down_sync(0xFFFFFFFFu, dsum, o);
    if ((threadIdx.x & 31) == 0) dred[threadIdx.x >> 5] = dsum;
    __syncthreads();
    if (threadIdx.x == 0) {
        double s = 0.0;
#pragma unroll
        for (int k = 0; k < 8; k++) s += dred[k];
        atomicAdd(&g_acc, s);
    }
}

// -------- 2) per-chunk nonzero counts (128 blocks x 128 bins) --------
__global__ void __launch_bounds__(128) k_scan1() {
    __shared__ int ws[4];
    int v = blockIdx.x * 128 + threadIdx.x;
    int f = (g_hist[v] > 0) ? 1 : 0;
#pragma unroll
    for (int o = 16; o > 0; o >>= 1) f += __shfl_down_sync(0xFFFFFFFFu, f, o);
    if ((threadIdx.x & 31) == 0) ws[threadIdx.x >> 5] = f;
    __syncthreads();
    if (threadIdx.x == 0)
        g_bsum[blockIdx.x] = ws[0] + ws[1] + ws[2] + ws[3];
}

// -------- 3) emit unique+count (+raw counts), gather z, meta+padding, re-zero hist --------
__global__ void __launch_bounds__(128) k_emit(const float* __restrict__ latent) {
    __shared__ int wbase[4];
    __shared__ int s_pre[4], s_tot[4];
    __shared__ int blkoff, total;
    const int tid  = threadIdx.x;
    const int lane = tid & 31;
    const int w    = tid >> 5;
    const int bid  = blockIdx.x;

    {
        int bs  = g_bsum[tid];
        int pre = (tid < bid) ? bs : 0;
#pragma unroll
        for (int o = 16; o > 0; o >>= 1) {
            pre += __shfl_down_sync(0xFFFFFFFFu, pre, o);
            bs  += __shfl_down_sync(0xFFFFFFFFu, bs, o);
        }
        if (lane == 0) { s_pre[w] = pre; s_tot[w] = bs; }
        __syncthreads();
        if (tid == 0) {
            blkoff = s_pre[0] + s_pre[1] + s_pre[2] + s_pre[3];
            total  = s_tot[0] + s_tot[1] + s_tot[2] + s_tot[3];
        }
    }

    const int v = bid * 128 + tid;
    const int c = g_hist[v];
    g_hist[v] = 0;                       // restore for next replay
    const bool flag = (c > 0);

    unsigned mask = __ballot_sync(0xFFFFFFFFu, flag);
    int excl = __popc(mask & ((1u << lane) - 1u));
    if (lane == 0) wbase[w] = __popc(mask);
    __syncthreads();
    if (tid == 0) {
        int s = 0;
#pragma unroll
        for (int k = 0; k < 4; k++) { int t = wbase[k]; wbase[k] = s; s += t; }
    }
    __syncthreads();

    if (flag) {
        int pos = blkoff + wbase[w] + excl;
        g_ucols[pos]  = v;
        g_cntf[pos]   = (float)c;
        g_cntraw[v]   = (float)c;        // raw-column weight for k_main
        float4 a = *reinterpret_cast<const float4*>(latent + (size_t)v * DD);
        float4 b = *reinterpret_cast<const float4*>(latent + (size_t)v * DD + 4);
        *reinterpret_cast<float4*>(g_z + (size_t)pos * DD)     = a;
        *reinterpret_cast<float4*>(g_z + (size_t)pos * DD + 4) = b;
        g_sq[pos] = a.x * a.x + a.y * a.y + a.z * a.z + a.w * a.w
                  + b.x * b.x + b.y * b.y + b.z * b.z + b.w * b.w;
    }

    // block 127: write meta + fill i-padding [U, UPADI) with zero-weight rows
    if (bid == 127) {
        const int U = total;
        if (tid == 0) {
            g_meta[0] = U;
            g_meta[1] = (U + TI - 1) / TI;   // n_ti
        }
        const int UPADI = ((U + TI - 1) / TI) * TI;
        float4 a = *reinterpret_cast<const float4*>(latent + (size_t)(NN - 1) * DD);
        float4 b = *reinterpret_cast<const float4*>(latent + (size_t)(NN - 1) * DD + 4);
        float sq = a.x * a.x + a.y * a.y + a.z * a.z + a.w * a.w
                 + b.x * b.x + b.y * b.y + b.z * b.z + b.w * b.w;
        for (int t = U + tid; t < UPADI; t += 128) {
            g_ucols[t] = NN - 1;
            g_cntf[t]  = 0.f;
            *reinterpret_cast<float4*>(g_z + (size_t)t * DD)     = a;
            *reinterpret_cast<float4*>(g_z + (size_t)t * DD + 4) = b;
            g_sq[t] = sq;
        }
    }
}

// -------- 4) main: unique-i x RAW-j tiles; fully coalesced streaming rel rows --------
__global__ void __launch_bounds__(TJ, 6) k_main(const float* __restrict__ rel,
                                                const float* __restrict__ latent) {
    const int ti = blockIdx.x >> 6;          // / NTJ
    if (ti >= g_meta[1]) return;             // n_ti
    const int tj = blockIdx.x & (NTJ - 1);
    const int iBase = ti * TI;
    const int jBase = tj * TJ;

    __shared__ float4 zi4[TI / 2][DD / 2];
    __shared__ float2 sqi[TI / 2];
    __shared__ float2 cip[TI / 2];
    __shared__ int    srow[TI];
    __shared__ float  red[8];

    const int tid = threadIdx.x;
    {
        int p = tid >> 3, d = tid & 7;
        int i0 = iBase + 2 * p;
        float2 pr = make_float2(g_z[(size_t)i0 * DD + d],
                                g_z[(size_t)(i0 + 1) * DD + d]);
        reinterpret_cast<float2*>(zi4)[p * DD + d] = pr;
    }
    if (tid < TI) srow[tid] = g_ucols[iBase + tid] << 14;   // *NN
    else if (tid < TI + 32) {
        int p = tid - TI;
        sqi[p] = make_float2(g_sq[iBase + 2 * p], g_sq[iBase + 2 * p + 1]);
    } else if (tid < TI + 64) {
        int p = tid - TI - 32;
        cip[p] = make_float2(g_cntf[iBase + 2 * p], g_cntf[iBase + 2 * p + 1]);
    }
    __syncthreads();

    const int col = jBase + tid;                 // RAW column: coalesced
    const float cj = g_cntraw[col];              // 0 for unsampled columns
    const float* relc = rel + col;

    float rv[2][8];
#pragma unroll
    for (int k = 0; k < 8; k++)
        rv[0][k] = __ldcs(relc + (size_t)srow[k]);   // streaming, no reuse

    // zj straight from latent (coalesced), sqj in-thread
    float4 zj0 = *reinterpret_cast<const float4*>(latent + (size_t)col * DD);
    float4 zj1 = *reinterpret_cast<const float4*>(latent + (size_t)col * DD + 4);
    const float sqj = zj0.x * zj0.x + zj0.y * zj0.y + zj0.z * zj0.z + zj0.w * zj0.w
                    + zj1.x * zj1.x + zj1.y * zj1.y + zj1.z * zj1.z + zj1.w * zj1.w;

    unsigned long long zm[8];
    zm[0] = pk2(-2.f * zj0.x, -2.f * zj0.x);
    zm[1] = pk2(-2.f * zj0.y, -2.f * zj0.y);
    zm[2] = pk2(-2.f * zj0.z, -2.f * zj0.z);
    zm[3] = pk2(-2.f * zj0.w, -2.f * zj0.w);
    zm[4] = pk2(-2.f * zj1.x, -2.f * zj1.x);
    zm[5] = pk2(-2.f * zj1.y, -2.f * zj1.y);
    zm[6] = pk2(-2.f * zj1.z, -2.f * zj1.z);
    zm[7] = pk2(-2.f * zj1.w, -2.f * zj1.w);
    const unsigned long long sqj2 = pk2(sqj, sqj);

    float acc0 = 0.f, acc1 = 0.f;
#pragma unroll
    for (int c = 0; c < 8; c++) {
        const int cur = c & 1;
        if (c < 7) {
#pragma unroll
            for (int k = 0; k < 8; k++)
                rv[cur ^ 1][k] = __ldcs(relc + (size_t)srow[(c + 1) * 8 + k]);
        }
#pragma unroll
        for (int pp = 0; pp < 4; pp++) {
            const int p = c * 4 + pp;
            const ulonglong2* zp = reinterpret_cast<const ulonglong2*>(&zi4[p][0]);
            ulonglong2 e0 = zp[0];
            ulonglong2 e1 = zp[1];
            unsigned long long d2 =
                add2(*reinterpret_cast<const unsigned long long*>(&sqi[p]), sqj2);
            d2 = fma2(e0.x, zm[0], d2);
            d2 = fma2(e0.y, zm[1], d2);
            d2 = fma2(e1.x, zm[2], d2);
            d2 = fma2(e1.y, zm[3], d2);
            ulonglong2 e2 = zp[2];
            ulonglong2 e3 = zp[3];
            d2 = fma2(e2.x, zm[4], d2);
            d2 = fma2(e2.y, zm[5], d2);
            d2 = fma2(e3.x, zm[6], d2);
            d2 = fma2(e3.y, zm[7], d2);

            float d2a, d2b;
            upk2(d2, d2a, d2b);
            float2 ci = cip[p];
            {
                float r  = rv[cur][2 * pp];
                float dv = fsqrt_ap(fmaxf(d2a, 0.f));
                float tt = dv - r;
                acc0 = fmaf(ci.x, (tt * tt) * frcp_ap(r), acc0);
            }
            {
                float r  = rv[cur][2 * pp + 1];
                float dv = fsqrt_ap(fmaxf(d2b, 0.f));
                float tt = dv - r;
                acc1 = fmaf(ci.y, (tt * tt) * frcp_ap(r), acc1);
            }
        }
    }
    float acc = (acc0 + acc1) * cj;

#pragma unroll
    for (int o = 16; o > 0; o >>= 1)
        acc += __shfl_down_sync(0xFFFFFFFFu, acc, o);
    if ((tid & 31) == 0) red[tid >> 5] = acc;
    __syncthreads();
    if (tid < 8) {
        float v = red[tid];
#pragma unroll
        for (int o = 4; o > 0; o >>= 1)
            v += __shfl_down_sync(0xFFu, v, o);
        if (tid == 0) atomicAdd(&g_acc, (double)v);
    }
}

// -------- 5) finalize + restore accumulator --------
__global__ void k_final(float* __restrict__ out) {
    out[0] = (float)sqrt(g_acc);
    g_acc = 0.0;
}

extern "C" void kernel_launch(void* const* d_in, const int* in_sizes, int n_in,
                              void* d_out, int out_size) {
    const float* latent = (const float*)d_in[0];   // [N, D] fp32
    const float* relmat = (const float*)d_in[1];   // [N, N] fp32
    const int*   sidx   = (const int*)d_in[2];     // [S]   int32
    float* out = (float*)d_out;
    (void)in_sizes; (void)n_in; (void)out_size;

    k_hist<<<SS / 256, 256>>>(sidx, relmat);
    k_scan1<<<128, 128>>>();
    k_emit<<<128, 128>>>(latent);
    k_main<<<(SS / TI) * NTJ, TJ>>>(relmat, latent);   // 128*64 blocks; extras exit
    k_final<<<1, 1>>>(out);
}

// round 15
// speedup vs baseline: 1.6477x; 1.6477x over previous
#include <cuda_runtime.h>
#include <cstdint>

#define NN 16384
#define DD 8
#define SS 8192
#define TI 64          // i-rows per tile (64-aligned padding)
#define TJ 256         // j-cols per tile (= blockDim.x; 256-aligned padding)

// -------- scratch (no allocations; zero-init at load; self-restoring) --------
__device__ int    g_hist[NN];        // re-zeroed by k_emit each run
__device__ int    g_bsum[128];       // overwritten by k_scan1 each run
__device__ int    g_ucols[SS];       // sorted unique sample values (padded)
__device__ float  g_cntf[SS];        // multiplicities as float (0 for padding)
__device__ float  g_z[SS * DD];      // gathered z (unique, sorted)
__device__ float  g_sq[SS];          // |z|^2
__device__ int    g_meta[4];         // U, n_tj, n_tiles, UPADJ
__device__ double g_acc;             // reset by k_final each run

// -------- packed f32x2 helpers --------
__device__ __forceinline__ unsigned long long pk2(float lo, float hi) {
    unsigned long long r;
    asm("mov.b64 %0, {%1, %2};" : "=l"(r) : "f"(lo), "f"(hi));
    return r;
}
__device__ __forceinline__ void upk2(unsigned long long v, float& lo, float& hi) {
    asm("mov.b64 {%0, %1}, %2;" : "=f"(lo), "=f"(hi) : "l"(v));
}
__device__ __forceinline__ unsigned long long fma2(unsigned long long a,
                                                   unsigned long long b,
                                                   unsigned long long c) {
    unsigned long long d;
    asm("fma.rn.f32x2 %0, %1, %2, %3;" : "=l"(d) : "l"(a), "l"(b), "l"(c));
    return d;
}
__device__ __forceinline__ unsigned long long add2(unsigned long long a,
                                                   unsigned long long b) {
    unsigned long long d;
    asm("add.rn.f32x2 %0, %1, %2;" : "=l"(d) : "l"(a), "l"(b));
    return d;
}
__device__ __forceinline__ float fsqrt_ap(float x) {
    float r; asm("sqrt.approx.f32 %0, %1;" : "=f"(r) : "f"(x)); return r;
}
__device__ __forceinline__ float frcp_ap(float x) {
    float r; asm("rcp.approx.f32 %0, %1;" : "=f"(r) : "f"(x)); return r;
}

// -------- 1) histogram + per-sample diagonal correction --------
__global__ void __launch_bounds__(256) k_hist(const int* __restrict__ idx,
                                              const float* __restrict__ rel) {
    __shared__ double dred[8];
    int t = blockIdx.x * blockDim.x + threadIdx.x;
    int v = idx[t];
    atomicAdd(&g_hist[v], 1);
    float r = __ldg(rel + (size_t)v * NN + v);
    double dsum = (double)r * (double)r / 5.0 - (double)r;
#pragma unroll
    for (int o = 16; o > 0; o >>= 1)
        dsum += __shfl_down_sync(0xFFFFFFFFu, dsum, o);
    if ((threadIdx.x & 31) == 0) dred[threadIdx.x >> 5] = dsum;
    __syncthreads();
    if (threadIdx.x == 0) {
        double s = 0.0;
#pragma unroll
        for (int k = 0; k < 8; k++) s += dred[k];
        atomicAdd(&g_acc, s);
    }
}

// -------- 2) per-chunk nonzero counts (128 blocks x 128 bins) --------
__global__ void __launch_bounds__(128) k_scan1() {
    __shared__ int ws[4];
    int v = blockIdx.x * 128 + threadIdx.x;
    int f = (g_hist[v] > 0) ? 1 : 0;
#pragma unroll
    for (int o = 16; o > 0; o >>= 1) f += __shfl_down_sync(0xFFFFFFFFu, f, o);
    if ((threadIdx.x & 31) == 0) ws[threadIdx.x >> 5] = f;
    __syncthreads();
    if (threadIdx.x == 0)
        g_bsum[blockIdx.x] = ws[0] + ws[1] + ws[2] + ws[3];
}

// -------- 3) emit unique+count, gather z, meta+padding, re-zero hist --------
__global__ void __launch_bounds__(128) k_emit(const float* __restrict__ latent) {
    __shared__ int wbase[4];
    __shared__ int s_pre[4], s_tot[4];
    __shared__ int blkoff, total;
    const int tid  = threadIdx.x;
    const int lane = tid & 31;
    const int w    = tid >> 5;
    const int bid  = blockIdx.x;

    {
        int bs  = g_bsum[tid];
        int pre = (tid < bid) ? bs : 0;
#pragma unroll
        for (int o = 16; o > 0; o >>= 1) {
            pre += __shfl_down_sync(0xFFFFFFFFu, pre, o);
            bs  += __shfl_down_sync(0xFFFFFFFFu, bs, o);
        }
        if (lane == 0) { s_pre[w] = pre; s_tot[w] = bs; }
        __syncthreads();
        if (tid == 0) {
            blkoff = s_pre[0] + s_pre[1] + s_pre[2] + s_pre[3];
            total  = s_tot[0] + s_tot[1] + s_tot[2] + s_tot[3];
        }
    }

    const int v = bid * 128 + tid;
    const int c = g_hist[v];
    g_hist[v] = 0;                       // restore for next replay
    const bool flag = (c > 0);

    unsigned mask = __ballot_sync(0xFFFFFFFFu, flag);
    int excl = __popc(mask & ((1u << lane) - 1u));
    if (lane == 0) wbase[w] = __popc(mask);
    __syncthreads();
    if (tid == 0) {
        int s = 0;
#pragma unroll
        for (int k = 0; k < 4; k++) { int t = wbase[k]; wbase[k] = s; s += t; }
    }
    __syncthreads();

    if (flag) {
        int pos = blkoff + wbase[w] + excl;
        g_ucols[pos] = v;
        g_cntf[pos]  = (float)c;
        float4 a = *reinterpret_cast<const float4*>(latent + (size_t)v * DD);
        float4 b = *reinterpret_cast<const float4*>(latent + (size_t)v * DD + 4);
        *reinterpret_cast<float4*>(g_z + (size_t)pos * DD)     = a;
        *reinterpret_cast<float4*>(g_z + (size_t)pos * DD + 4) = b;
        g_sq[pos] = a.x * a.x + a.y * a.y + a.z * a.z + a.w * a.w
                  + b.x * b.x + b.y * b.y + b.z * b.z + b.w * b.w;
    }

    // block 127: write meta (dual padding) + fill padding [U, UPADJ)
    if (bid == 127) {
        const int U = total;
        if (tid == 0) {
            int n_ti = (U + TI - 1) / TI;   // i-tiles: 64-aligned
            int n_tj = (U + TJ - 1) / TJ;   // j-tiles: 256-aligned
            g_meta[0] = U;
            g_meta[1] = n_tj;
            g_meta[2] = n_ti * n_tj;
            g_meta[3] = n_tj * TJ;
        }
        const int UPADJ = ((U + TJ - 1) / TJ) * TJ;
        float4 a = *reinterpret_cast<const float4*>(latent + (size_t)(NN - 1) * DD);
        float4 b = *reinterpret_cast<const float4*>(latent + (size_t)(NN - 1) * DD + 4);
        float sq = a.x * a.x + a.y * a.y + a.z * a.z + a.w * a.w
                 + b.x * b.x + b.y * b.y + b.z * b.z + b.w * b.w;
        for (int t = U + tid; t < UPADJ; t += 128) {
            g_ucols[t] = NN - 1;
            g_cntf[t]  = 0.f;
            *reinterpret_cast<float4*>(g_z + (size_t)t * DD)     = a;
            *reinterpret_cast<float4*>(g_z + (size_t)t * DD + 4) = b;
            g_sq[t] = sq;
        }
    }
}

// -------- 4) main: 64x256 tiles, occ 6, __ldcs streaming rel loads --------
__global__ void __launch_bounds__(TJ, 6) k_main(const float* __restrict__ rel) {
    const int n_tiles = g_meta[2];
    if ((int)blockIdx.x >= n_tiles) return;
    const int n_tj = g_meta[1];
    const int ti = blockIdx.x / n_tj;
    const int tj = blockIdx.x - ti * n_tj;
    const int iBase = ti * TI;
    const int jBase = tj * TJ;

    __shared__ float4 zi4[TI / 2][DD / 2];
    __shared__ float2 sqi[TI / 2];
    __shared__ float2 cip[TI / 2];
    __shared__ int    srow[TI];
    __shared__ float  red[8];

    const int tid = threadIdx.x;
    {
        int p = tid >> 3, d = tid & 7;
        int i0 = iBase + 2 * p;
        float2 pr = make_float2(g_z[(size_t)i0 * DD + d],
                                g_z[(size_t)(i0 + 1) * DD + d]);
        reinterpret_cast<float2*>(zi4)[p * DD + d] = pr;
    }
    if (tid < TI) srow[tid] = g_ucols[iBase + tid] << 14;   // *NN
    else if (tid < TI + 32) {
        int p = tid - TI;
        sqi[p] = make_float2(g_sq[iBase + 2 * p], g_sq[iBase + 2 * p + 1]);
    } else if (tid < TI + 64) {
        int p = tid - TI - 32;
        cip[p] = make_float2(g_cntf[iBase + 2 * p], g_cntf[iBase + 2 * p + 1]);
    }
    __syncthreads();

    const int j   = jBase + tid;
    const int col = g_ucols[j];
    const float cj = g_cntf[j];
    const float* relc = rel + col;

    float rv[2][8];
#pragma unroll
    for (int k = 0; k < 8; k++)
        rv[0][k] = __ldcs(relc + (size_t)srow[k]);          // streaming: no reuse

    float4 zj0 = *reinterpret_cast<const float4*>(g_z + (size_t)j * DD);
    float4 zj1 = *reinterpret_cast<const float4*>(g_z + (size_t)j * DD + 4);
    const float sqj = g_sq[j];

    unsigned long long zm[8];
    zm[0] = pk2(-2.f * zj0.x, -2.f * zj0.x);
    zm[1] = pk2(-2.f * zj0.y, -2.f * zj0.y);
    zm[2] = pk2(-2.f * zj0.z, -2.f * zj0.z);
    zm[3] = pk2(-2.f * zj0.w, -2.f * zj0.w);
    zm[4] = pk2(-2.f * zj1.x, -2.f * zj1.x);
    zm[5] = pk2(-2.f * zj1.y, -2.f * zj1.y);
    zm[6] = pk2(-2.f * zj1.z, -2.f * zj1.z);
    zm[7] = pk2(-2.f * zj1.w, -2.f * zj1.w);
    const unsigned long long sqj2 = pk2(sqj, sqj);

    float acc0 = 0.f, acc1 = 0.f;
#pragma unroll
    for (int c = 0; c < 8; c++) {
        const int cur = c & 1;
        if (c < 7) {
#pragma unroll
            for (int k = 0; k < 8; k++)
                rv[cur ^ 1][k] = __ldcs(relc + (size_t)srow[(c + 1) * 8 + k]);
        }
#pragma unroll
        for (int pp = 0; pp < 4; pp++) {
            const int p = c * 4 + pp;
            const ulonglong2* zp = reinterpret_cast<const ulonglong2*>(&zi4[p][0]);
            ulonglong2 e0 = zp[0];
            ulonglong2 e1 = zp[1];
            unsigned long long d2 =
                add2(*reinterpret_cast<const unsigned long long*>(&sqi[p]), sqj2);
            d2 = fma2(e0.x, zm[0], d2);
            d2 = fma2(e0.y, zm[1], d2);
            d2 = fma2(e1.x, zm[2], d2);
            d2 = fma2(e1.y, zm[3], d2);
            ulonglong2 e2 = zp[2];
            ulonglong2 e3 = zp[3];
            d2 = fma2(e2.x, zm[4], d2);
            d2 = fma2(e2.y, zm[5], d2);
            d2 = fma2(e3.x, zm[6], d2);
            d2 = fma2(e3.y, zm[7], d2);

            float d2a, d2b;
            upk2(d2, d2a, d2b);
            float2 ci = cip[p];
            {
                float r  = rv[cur][2 * pp];
                float dv = fsqrt_ap(fmaxf(d2a, 0.f));
                float tt = dv - r;
                acc0 = fmaf(ci.x, (tt * tt) * frcp_ap(r), acc0);
            }
            {
                float r  = rv[cur][2 * pp + 1];
                float dv = fsqrt_ap(fmaxf(d2b, 0.f));
                float tt = dv - r;
                acc1 = fmaf(ci.y, (tt * tt) * frcp_ap(r), acc1);
            }
        }
    }
    float acc = (acc0 + acc1) * cj;

#pragma unroll
    for (int o = 16; o > 0; o >>= 1)
        acc += __shfl_down_sync(0xFFFFFFFFu, acc, o);
    if ((tid & 31) == 0) red[tid >> 5] = acc;
    __syncthreads();
    if (tid < 8) {
        float v = red[tid];
#pragma unroll
        for (int o = 4; o > 0; o >>= 1)
            v += __shfl_down_sync(0xFFu, v, o);
        if (tid == 0) atomicAdd(&g_acc, (double)v);
    }
}

// -------- 5) finalize + restore accumulator --------
__global__ void k_final(float* __restrict__ out) {
    out[0] = (float)sqrt(g_acc);
    g_acc = 0.0;
}

extern "C" void kernel_launch(void* const* d_in, const int* in_sizes, int n_in,
                              void* d_out, int out_size) {
    const float* latent = (const float*)d_in[0];   // [N, D] fp32
    const float* relmat = (const float*)d_in[1];   // [N, N] fp32
    const int*   sidx   = (const int*)d_in[2];     // [S]   int32
    float* out = (float*)d_out;
    (void)in_sizes; (void)n_in; (void)out_size;

    k_hist<<<SS / 256, 256>>>(sidx, relmat);
    k_scan1<<<128, 128>>>();
    k_emit<<<128, 128>>>(latent);
    k_main<<<(SS / TI) * (SS / TJ), TJ>>>(relmat);
    k_final<<<1, 1>>>(out);
}